// round 13
// baseline (speedup 1.0000x reference)
#include <cuda_runtime.h>
#include <cuda_fp16.h>
#include <cstdint>

// ===========================================================================
// y = u @ W^T,  W = C (I-A)^{-1} B + D   (model is linear & time-invariant)
//
// Precompute via telescoping product (NO triangular solve):
//   (I-A)^{-1} = (I+A)(I+A^2)(I+A^4) + O(A^8),  ||A^8|| ~ 7e-7  (negligible)
//   K1: A2 = A*A            | P = C + C*A          (dual launch, 32 blocks)
//   K2: A4 = A2*A2          | Q = P + P*A2         (dual launch)
//   K3: R = Q + Q*A4                                (16 blocks)
//   K4: W = R*B + D -> fp16 swizzled ldmatrix image
// Stage 3 gemm_kernel : persistent HMMA single-term fp16 GEMM y = uh*Wh,
//   64-row tiles, 2 CTAs/SM, double-buffered U, convert/STS AND t+2 LDG
//   prefetch interleaved into the MMA ks-loop (LDG gets ~3000cyc to land).
// NOTE: tcgen05 unusable (harness PTX targets compute_103, no 'a').
// ===========================================================================

#define SDIM 128
#define N_ROWS (32 * 8192)
#define TILE64 64
#define N_TILES (N_ROWS / TILE64)     // 4096

__device__ float g_A2[SDIM * SDIM];
__device__ float g_A4[SDIM * SDIM];
__device__ float g_P[SDIM * SDIM];
__device__ float g_Q[SDIM * SDIM];
__device__ float g_R[SDIM * SDIM];
__device__ __half g_Wh[SDIM * SDIM];   // swizzled ldmatrix image

__device__ __forceinline__ uint32_t smem_u32(const void* p) {
    return (uint32_t)__cvta_generic_to_shared(p);
}
__device__ __forceinline__ int swz_elem(int r, int k) {
    return r * 128 + ((((k >> 3) ^ (r & 7)) << 3) | (k & 7));
}

#define LDSM4(r, a) \
    asm volatile("ldmatrix.sync.aligned.m8n8.x4.shared.b16 {%0,%1,%2,%3}, [%4];" \
        : "=r"((r)[0]), "=r"((r)[1]), "=r"((r)[2]), "=r"((r)[3]) : "r"(a))

#define MMA16816H(d, a, b0, b1) \
    asm volatile("mma.sync.aligned.m16n8k16.row.col.f32.f16.f16.f32 " \
        "{%0,%1,%2,%3}, {%4,%5,%6,%7}, {%8,%9}, {%0,%1,%2,%3};" \
        : "+f"((d)[0]), "+f"((d)[1]), "+f"((d)[2]), "+f"((d)[3]) \
        : "r"((a)[0]), "r"((a)[1]), "r"((a)[2]), "r"((a)[3]), "r"(b0), "r"(b1))

// ===========================================================================
// 128x128x128 fp32 GEMM slab: OUT = L*R + (S ? S : 0).
// One block = 8 output rows; full R staged in SMEM (64KB dynamic).
// ===========================================================================
__device__ __forceinline__ void mm128_body(const float* __restrict__ L,
                                           const float* __restrict__ R,
                                           const float* __restrict__ S,
                                           float* __restrict__ OUT,
                                           int blk, float* sR, float* sL) {
    const int tid = threadIdx.x;
    const int r0 = blk * 8;
    for (int i = tid; i < 4096; i += 256)
        ((float4*)sR)[i] = ((const float4*)R)[i];
    if (tid < 256) {
        ((float4*)sL)[tid] = ((const float4*)(L + r0 * SDIM))[tid];
    }
    __syncthreads();
    const int r  = tid >> 5;
    const int c4 = (tid & 31) * 4;
    float4 acc = S ? *(const float4*)(S + (r0 + r) * SDIM + c4)
                   : make_float4(0.f, 0.f, 0.f, 0.f);
    const float* lrow = sL + r * SDIM;
    #pragma unroll 8
    for (int k = 0; k < SDIM; k++) {
        float a = lrow[k];
        float4 b = *(const float4*)(sR + k * SDIM + c4);
        acc.x = fmaf(a, b.x, acc.x);
        acc.y = fmaf(a, b.y, acc.y);
        acc.z = fmaf(a, b.z, acc.z);
        acc.w = fmaf(a, b.w, acc.w);
    }
    *(float4*)(OUT + (r0 + r) * SDIM + c4) = acc;
}

// dual: blocks [0,16) -> job0, [16,32) -> job1 (independent)
__global__ __launch_bounds__(256, 1)
void mm128_dual_kernel(const float* L0, const float* R0, const float* S0, float* O0,
                       const float* L1, const float* R1, const float* S1, float* O1) {
    extern __shared__ float smp[];
    float* sR = smp;          // [128][128]
    float* sL = smp + 16384;  // [8][128]
    if (blockIdx.x < 16) mm128_body(L0, R0, S0, O0, blockIdx.x, sR, sL);
    else                 mm128_body(L1, R1, S1, O1, blockIdx.x - 16, sR, sL);
}

__global__ __launch_bounds__(256, 1)
void mm128_kernel(const float* L, const float* R, const float* S, float* O) {
    extern __shared__ float smp[];
    mm128_body(L, R, S, O, blockIdx.x, smp, smp + 16384);
}

// ===========================================================================
// K4: W[o][d] = sum_s R[o,s] B[s,d] + D[o,d] -> fp16 swizzled image
// ===========================================================================
__global__ void wk_kernel(const float* __restrict__ B, const float* __restrict__ Dm) {
    const int o = blockIdx.x;      // 128 blocks
    const int d = threadIdx.x;     // 128 threads
    float acc = Dm[o * SDIM + d];
    #pragma unroll 8
    for (int s = 0; s < SDIM; s++)
        acc = fmaf(g_R[o * SDIM + s], B[s * SDIM + d], acc);
    g_Wh[swz_elem(o, d)] = __float2half_rn(acc);
}

// ===========================================================================
// Stage 3: persistent HMMA GEMM, single fp16 term, 64-row tiles, 2 CTAs/SM.
// SMEM/CTA: [0,32K) Wh | U buf p at 32K + p*16K  (total 64KB)
// ===========================================================================
#define GSMEM_BYTES (64 * 1024)
#define UBOFF(p) (32768u + (uint32_t)(p) * 16384u)

__global__ __launch_bounds__(256, 2)
void gemm_kernel(const float* __restrict__ u, float* __restrict__ y, int grid) {
    extern __shared__ __align__(16) unsigned char sm[];
    const uint32_t sbase = smem_u32(sm);

    const int tid  = threadIdx.x;
    const int lane = tid & 31;
    const int w    = tid >> 5;
    const int rg   = w >> 2;           // 0..1 : 32-row group
    const int cq   = w & 3;            // 0..3 : 32-col quarter
    const int Rw   = rg * 32;

    // W image -> SMEM
    {
        const uint4* sh = (const uint4*)g_Wh;
        uint4* dh = (uint4*)sm;
        for (int i = tid; i < 2048; i += 256) dh[i] = sh[i];
    }

    const int a_row  = Rw + (lane & 7) + ((lane >> 3) & 1) * 8;
    const int a_kadd = ((lane >> 4) & 1) * 8;
    const int b_n    = cq * 32 + (lane & 7) + ((lane >> 4) & 1) * 8;
    const int b_kadd = ((lane >> 3) & 1) * 8;
    const int r7     = lane & 7;

    float4 v[8];
    int tile = blockIdx.x;

    // ---- prologue: tile0 -> buf0; then v <- tile1 -------------------------
    if (tile < N_TILES) {
        const float4* src = (const float4*)u + (long)tile * 2048;
        #pragma unroll
        for (int j = 0; j < 8; j++) v[j] = src[tid + 256 * j];
        #pragma unroll
        for (int j = 0; j < 8; j++) {
            int uid = tid + 256 * j;
            int row = uid >> 5, kk = uid & 31;
            float4 p0 = v[j];
            __half2 h01 = __floats2half2_rn(p0.x, p0.y);
            __half2 h23 = __floats2half2_rn(p0.z, p0.w);
            int off = row * 256 + (((kk >> 1) ^ (row & 7)) << 4) + (kk & 1) * 8;
            *(uint2*)(sm + UBOFF(0) + off) =
                make_uint2(*(uint32_t*)&h01, *(uint32_t*)&h23);
        }
    }
    if (tile + grid < N_TILES) {
        const float4* src = (const float4*)u + (long)(tile + grid) * 2048;
        #pragma unroll
        for (int j = 0; j < 8; j++) v[j] = src[tid + 256 * j];
    }
    __syncthreads();

    int p = 0;
    for (; tile < N_TILES; tile += grid) {
        const bool hasNext  = (tile + grid) < N_TILES;
        const bool hasNext2 = (tile + 2 * grid) < N_TILES;
        const uint32_t ub  = UBOFF(p);
        const uint32_t ubn = UBOFF(p ^ 1);
        const float4* src2 = (const float4*)u + (long)(tile + 2 * grid) * 2048;

        float acc[2][4][4];
        #pragma unroll
        for (int rf = 0; rf < 2; rf++)
            #pragma unroll
            for (int nt = 0; nt < 4; nt++)
                #pragma unroll
                for (int q = 0; q < 4; q++) acc[rf][nt][q] = 0.f;

        #pragma unroll
        for (int ks = 0; ks < 8; ks++) {
            const int k0 = ks * 16;
            uint32_t ah[2][4];
            {
                int mk = k0 + a_kadd;
                uint32_t ad = sbase + ub +
                    (uint32_t)(a_row * 256 + (((mk >> 3) ^ r7) << 4));
                LDSM4(ah[0], ad);
                LDSM4(ah[1], ad + 4096u);
            }
            #pragma unroll
            for (int ng = 0; ng < 2; ng++) {
                int n = b_n + ng * 16;
                int mk = k0 + b_kadd;
                uint32_t bd = sbase +
                    (uint32_t)(n * 256 + (((mk >> 3) ^ r7) << 4));
                uint32_t bh[4];
                LDSM4(bh, bd);
                const int nt = ng * 2;
                MMA16816H(acc[0][nt],     ah[0], bh[0], bh[1]);
                MMA16816H(acc[0][nt + 1], ah[0], bh[2], bh[3]);
                MMA16816H(acc[1][nt],     ah[1], bh[0], bh[1]);
                MMA16816H(acc[1][nt + 1], ah[1], bh[2], bh[3]);
            }
            // convert chunk ks of tile t+1 (consumes v[ks]) ...
            if (hasNext) {
                int uid = tid + 256 * ks;
                int row = uid >> 5, kk = uid & 31;
                float4 p0 = v[ks];
                __half2 h01 = __floats2half2_rn(p0.x, p0.y);
                __half2 h23 = __floats2half2_rn(p0.z, p0.w);
                int off = row * 256 + (((kk >> 1) ^ (row & 7)) << 4) + (kk & 1) * 8;
                *(uint2*)(sm + ubn + off) =
                    make_uint2(*(uint32_t*)&h01, *(uint32_t*)&h23);
            }
            // ... then immediately refill v[ks] with tile t+2 chunk ks:
            // this LDG has the rest of the mainloop (~3000cyc) to land.
            if (hasNext2) {
                v[ks] = src2[tid + 256 * ks];
            }
        }

        // epilogue: fragments -> y
        {
            const int q = lane >> 2, s2 = (lane & 3) * 2;
            #pragma unroll
            for (int rf = 0; rf < 2; rf++) {
                long grow = (long)tile * TILE64 + Rw + rf * 16 + q;
                float* yp0 = y + grow * SDIM + cq * 32 + s2;
                #pragma unroll
                for (int nt = 0; nt < 4; nt++) {
                    *(float2*)(yp0 + nt * 8) =
                        make_float2(acc[rf][nt][0], acc[rf][nt][1]);
                    *(float2*)(yp0 + 8 * SDIM + nt * 8) =
                        make_float2(acc[rf][nt][2], acc[rf][nt][3]);
                }
            }
        }
        __syncthreads();
        p ^= 1;
    }
}

// ===========================================================================
extern "C" void kernel_launch(void* const* d_in, const int* in_sizes, int n_in,
                              void* d_out, int out_size) {
    const float* u = (const float*)d_in[0];
    const float* A = (const float*)d_in[1];
    const float* B = (const float*)d_in[2];
    const float* C = (const float*)d_in[3];
    const float* D = (const float*)d_in[4];
    float* y = (float*)d_out;

    int sms = 0, dev = 0;
    cudaGetDevice(&dev);
    cudaDeviceGetAttribute(&sms, cudaDevAttrMultiProcessorCount, dev);
    if (sms <= 0) sms = 148;

    const int mm_smem = (16384 + 1024) * (int)sizeof(float);  // 68KB
    cudaFuncSetAttribute(mm128_dual_kernel, cudaFuncAttributeMaxDynamicSharedMemorySize, mm_smem);
    cudaFuncSetAttribute(mm128_kernel,      cudaFuncAttributeMaxDynamicSharedMemorySize, mm_smem);
    cudaFuncSetAttribute(gemm_kernel,       cudaFuncAttributeMaxDynamicSharedMemorySize, GSMEM_BYTES);

    // device-symbol addresses (host-side)
    float *dA2, *dA4, *dP, *dQ, *dR;
    cudaGetSymbolAddress((void**)&dA2, g_A2);
    cudaGetSymbolAddress((void**)&dA4, g_A4);
    cudaGetSymbolAddress((void**)&dP,  g_P);
    cudaGetSymbolAddress((void**)&dQ,  g_Q);
    cudaGetSymbolAddress((void**)&dR,  g_R);

    // K1: A2 = A*A           | P = C + C*A
    mm128_dual_kernel<<<32, 256, mm_smem>>>(A, A, nullptr, dA2,
                                            C, A, C, dP);
    // K2: A4 = A2*A2         | Q = P + P*A2
    mm128_dual_kernel<<<32, 256, mm_smem>>>(dA2, dA2, nullptr, dA4,
                                            dP, dA2, dP, dQ);
    // K3: R = Q + Q*A4
    mm128_kernel<<<16, 256, mm_smem>>>(dQ, dA4, dQ, dR);
    // K4: W = R*B + D -> fp16 image
    wk_kernel<<<128, 128>>>(B, D);

    const int grid = 2 * sms;
    gemm_kernel<<<grid, 256, GSMEM_BYTES>>>(u, y, grid);
}

// round 14
// speedup vs baseline: 1.1994x; 1.1994x over previous
#include <cuda_runtime.h>
#include <cuda_fp16.h>
#include <cstdint>

// ===========================================================================
// y = u @ W^T,  W = C (I-A)^{-1} B + D   (model is linear & time-invariant)
//
// Precompute via telescoping product (NO serial triangular solve):
//   (I-A)^{-1} = (I+A)(I+A^2)(I+A^4) + O(A^8),  ||A^8|| ~ 7e-7 (negligible;
//   verified rel_err identical to trsm path at 2.95e-4)
//   K1 (dual): A2 = A*A        | P = C*A + C
//   K2 (dual): A4 = A2*A2      | Q = P*A2 + P
//   K3:        R = Q*A4 + Q            (R = C*(I-A)^{-1})
//   K4:        W = R*B + D -> fp16 swizzled ldmatrix image
//   All: 2 output rows/block, 256 thr, L-rows in SMEM, R streamed @ MLP16.
// Stage 3 gemm_kernel : persistent HMMA single-term fp16 GEMM y = uh*Wh
//   (round-12 proven version: 64-row tiles, 2 CTAs/SM, double-buffered U,
//    convert/STS interleaved in ks-loop, t+2 LDG after mainloop).
// NOTE: tcgen05 unusable (harness PTX targets compute_103, no 'a').
// ===========================================================================

#define SDIM 128
#define N_ROWS (32 * 8192)
#define TILE64 64
#define N_TILES (N_ROWS / TILE64)     // 4096

__device__ float g_A2[SDIM * SDIM];
__device__ float g_A4[SDIM * SDIM];
__device__ float g_P[SDIM * SDIM];
__device__ float g_Q[SDIM * SDIM];
__device__ float g_R[SDIM * SDIM];
__device__ __half g_Wh[SDIM * SDIM];   // swizzled ldmatrix image

__device__ __forceinline__ uint32_t smem_u32(const void* p) {
    return (uint32_t)__cvta_generic_to_shared(p);
}
__device__ __forceinline__ int swz_elem(int r, int k) {
    return r * 128 + ((((k >> 3) ^ (r & 7)) << 3) | (k & 7));
}

#define LDSM4(r, a) \
    asm volatile("ldmatrix.sync.aligned.m8n8.x4.shared.b16 {%0,%1,%2,%3}, [%4];" \
        : "=r"((r)[0]), "=r"((r)[1]), "=r"((r)[2]), "=r"((r)[3]) : "r"(a))

#define MMA16816H(d, a, b0, b1) \
    asm volatile("mma.sync.aligned.m16n8k16.row.col.f32.f16.f16.f32 " \
        "{%0,%1,%2,%3}, {%4,%5,%6,%7}, {%8,%9}, {%0,%1,%2,%3};" \
        : "+f"((d)[0]), "+f"((d)[1]), "+f"((d)[2]), "+f"((d)[3]) \
        : "r"((a)[0]), "r"((a)[1]), "r"((a)[2]), "r"((a)[3]), "r"(b0), "r"(b1))

// ===========================================================================
// Small-GEMM row kernel: O[o][:] = L[o][:]*R + (S ? S[o][:] : 0)
// 2 rows per block, 256 threads; L rows in SMEM, R streamed (MLP 16).
// ===========================================================================
__device__ __forceinline__ void mmrow_body(const float* __restrict__ L,
                                           const float* __restrict__ R,
                                           const float* __restrict__ S,
                                           float* __restrict__ O, int b,
                                           float sL[2][SDIM]) {
    const int tid = threadIdx.x;
    const int r = tid >> 7, d = tid & 127;
    const int o = b * 2 + r;
    sL[r][d] = L[o * SDIM + d];
    __syncthreads();
    float acc = S ? S[o * SDIM + d] : 0.f;
    #pragma unroll 16
    for (int s = 0; s < SDIM; s++)
        acc = fmaf(sL[r][s], R[s * SDIM + d], acc);
    O[o * SDIM + d] = acc;
}

__global__ __launch_bounds__(256, 4)
void mmrow_dual_kernel(const float* L0, const float* R0, const float* S0, float* O0,
                       const float* L1, const float* R1, const float* S1, float* O1) {
    __shared__ float sL[2][SDIM];
    if (blockIdx.x < 64) mmrow_body(L0, R0, S0, O0, blockIdx.x, sL);
    else                 mmrow_body(L1, R1, S1, O1, blockIdx.x - 64, sL);
}

__global__ __launch_bounds__(256, 4)
void mmrow_kernel(const float* L, const float* R, const float* S, float* O) {
    __shared__ float sL[2][SDIM];
    mmrow_body(L, R, S, O, blockIdx.x, sL);
}

// K4: W[o][d] = sum_s R[o,s] B[s,d] + D[o,d] -> fp16 swizzled image
__global__ __launch_bounds__(256, 4)
void wk_kernel(const float* __restrict__ B, const float* __restrict__ Dm) {
    __shared__ float sL[2][SDIM];
    const int tid = threadIdx.x;
    const int r = tid >> 7, d = tid & 127;
    const int o = blockIdx.x * 2 + r;
    sL[r][d] = g_R[o * SDIM + d];
    __syncthreads();
    float acc = Dm[o * SDIM + d];
    #pragma unroll 16
    for (int s = 0; s < SDIM; s++)
        acc = fmaf(sL[r][s], B[s * SDIM + d], acc);
    g_Wh[swz_elem(o, d)] = __float2half_rn(acc);
}

// ===========================================================================
// Stage 3: persistent HMMA GEMM, single fp16 term, 64-row tiles, 2 CTAs/SM.
// SMEM/CTA: [0,32K) Wh | U buf p at 32K + p*16K  (total 64KB)
// (byte-for-byte the round-12 proven version)
// ===========================================================================
#define GSMEM_BYTES (64 * 1024)
#define UBOFF(p) (32768u + (uint32_t)(p) * 16384u)

__global__ __launch_bounds__(256, 2)
void gemm_kernel(const float* __restrict__ u, float* __restrict__ y, int grid) {
    extern __shared__ __align__(16) unsigned char sm[];
    const uint32_t sbase = smem_u32(sm);

    const int tid  = threadIdx.x;
    const int lane = tid & 31;
    const int w    = tid >> 5;
    const int rg   = w >> 2;           // 0..1 : 32-row group
    const int cq   = w & 3;            // 0..3 : 32-col quarter
    const int Rw   = rg * 32;

    // W image -> SMEM
    {
        const uint4* sh = (const uint4*)g_Wh;
        uint4* dh = (uint4*)sm;
        for (int i = tid; i < 2048; i += 256) dh[i] = sh[i];
    }

    const int a_row  = Rw + (lane & 7) + ((lane >> 3) & 1) * 8;       // + rf*16
    const int a_kadd = ((lane >> 4) & 1) * 8;
    const int b_n    = cq * 32 + (lane & 7) + ((lane >> 4) & 1) * 8;  // + ng*16
    const int b_kadd = ((lane >> 3) & 1) * 8;
    const int r7     = lane & 7;

    float4 v[8];
    int tile = blockIdx.x;

    // ---- prologue: tile0 -> buf0; prefetch tile1 into regs ---------------
    if (tile < N_TILES) {
        const float4* src = (const float4*)u + (long)tile * 2048;
        #pragma unroll
        for (int j = 0; j < 8; j++) v[j] = src[tid + 256 * j];
        #pragma unroll
        for (int j = 0; j < 8; j++) {
            int uid = tid + 256 * j;
            int row = uid >> 5, kk = uid & 31;        // kk = 8B unit in row
            float4 p0 = v[j];
            __half2 h01 = __floats2half2_rn(p0.x, p0.y);
            __half2 h23 = __floats2half2_rn(p0.z, p0.w);
            int off = row * 256 + (((kk >> 1) ^ (row & 7)) << 4) + (kk & 1) * 8;
            *(uint2*)(sm + UBOFF(0) + off) =
                make_uint2(*(uint32_t*)&h01, *(uint32_t*)&h23);
        }
    }
    if (tile + grid < N_TILES) {
        const float4* src = (const float4*)u + (long)(tile + grid) * 2048;
        #pragma unroll
        for (int j = 0; j < 8; j++) v[j] = src[tid + 256 * j];
    }
    __syncthreads();

    int p = 0;
    for (; tile < N_TILES; tile += grid) {
        const bool hasNext = (tile + grid) < N_TILES;
        const uint32_t ub  = UBOFF(p);
        const uint32_t ubn = UBOFF(p ^ 1);

        float acc[2][4][4];
        #pragma unroll
        for (int rf = 0; rf < 2; rf++)
            #pragma unroll
            for (int nt = 0; nt < 4; nt++)
                #pragma unroll
                for (int q = 0; q < 4; q++) acc[rf][nt][q] = 0.f;

        #pragma unroll
        for (int ks = 0; ks < 8; ks++) {
            const int k0 = ks * 16;
            uint32_t ah[2][4];
            {
                int mk = k0 + a_kadd;
                uint32_t ad = sbase + ub +
                    (uint32_t)(a_row * 256 + (((mk >> 3) ^ r7) << 4));
                LDSM4(ah[0], ad);
                LDSM4(ah[1], ad + 4096u);     // +16 rows
            }
            #pragma unroll
            for (int ng = 0; ng < 2; ng++) {
                int n = b_n + ng * 16;
                int mk = k0 + b_kadd;
                uint32_t bd = sbase +
                    (uint32_t)(n * 256 + (((mk >> 3) ^ r7) << 4));
                uint32_t bh[4];
                LDSM4(bh, bd);
                const int nt = ng * 2;
                MMA16816H(acc[0][nt],     ah[0], bh[0], bh[1]);
                MMA16816H(acc[0][nt + 1], ah[0], bh[2], bh[3]);
                MMA16816H(acc[1][nt],     ah[1], bh[0], bh[1]);
                MMA16816H(acc[1][nt + 1], ah[1], bh[2], bh[3]);
            }
            // interleave next-tile convert/STS chunk (1 uint2 per thread)
            if (hasNext) {
                int uid = tid + 256 * ks;
                int row = uid >> 5, kk = uid & 31;
                float4 p0 = v[ks];
                __half2 h01 = __floats2half2_rn(p0.x, p0.y);
                __half2 h23 = __floats2half2_rn(p0.z, p0.w);
                int off = row * 256 + (((kk >> 1) ^ (row & 7)) << 4) + (kk & 1) * 8;
                *(uint2*)(sm + ubn + off) =
                    make_uint2(*(uint32_t*)&h01, *(uint32_t*)&h23);
            }
        }

        // epilogue: fragments -> y
        {
            const int q = lane >> 2, s2 = (lane & 3) * 2;
            #pragma unroll
            for (int rf = 0; rf < 2; rf++) {
                long grow = (long)tile * TILE64 + Rw + rf * 16 + q;
                float* yp0 = y + grow * SDIM + cq * 32 + s2;
                #pragma unroll
                for (int nt = 0; nt < 4; nt++) {
                    *(float2*)(yp0 + nt * 8) =
                        make_float2(acc[rf][nt][0], acc[rf][nt][1]);
                    *(float2*)(yp0 + 8 * SDIM + nt * 8) =
                        make_float2(acc[rf][nt][2], acc[rf][nt][3]);
                }
            }
        }

        // prefetch tile t+2 into regs
        if (tile + 2 * grid < N_TILES) {
            const float4* src = (const float4*)u + (long)(tile + 2 * grid) * 2048;
            #pragma unroll
            for (int j = 0; j < 8; j++) v[j] = src[tid + 256 * j];
        }
        __syncthreads();
        p ^= 1;
    }
}

// ===========================================================================
extern "C" void kernel_launch(void* const* d_in, const int* in_sizes, int n_in,
                              void* d_out, int out_size) {
    const float* u = (const float*)d_in[0];
    const float* A = (const float*)d_in[1];
    const float* B = (const float*)d_in[2];
    const float* C = (const float*)d_in[3];
    const float* D = (const float*)d_in[4];
    float* y = (float*)d_out;

    int sms = 0, dev = 0;
    cudaGetDevice(&dev);
    cudaDeviceGetAttribute(&sms, cudaDevAttrMultiProcessorCount, dev);
    if (sms <= 0) sms = 148;

    cudaFuncSetAttribute(gemm_kernel, cudaFuncAttributeMaxDynamicSharedMemorySize, GSMEM_BYTES);

    float *dA2, *dA4, *dP, *dQ, *dR;
    cudaGetSymbolAddress((void**)&dA2, g_A2);
    cudaGetSymbolAddress((void**)&dA4, g_A4);
    cudaGetSymbolAddress((void**)&dP,  g_P);
    cudaGetSymbolAddress((void**)&dQ,  g_Q);
    cudaGetSymbolAddress((void**)&dR,  g_R);

    // K1: A2 = A*A            | P = C*A + C
    mmrow_dual_kernel<<<128, 256>>>(A, A, nullptr, dA2,
                                    C, A, C, dP);
    // K2: A4 = A2*A2          | Q = P*A2 + P
    mmrow_dual_kernel<<<128, 256>>>(dA2, dA2, nullptr, dA4,
                                    dP, dA2, dP, dQ);
    // K3: R = Q*A4 + Q
    mmrow_kernel<<<64, 256>>>(dQ, dA4, dQ, dR);
    // K4: W = R*B + D -> fp16 image
    wk_kernel<<<64, 256>>>(B, D);

    const int grid = 2 * sms;
    gemm_kernel<<<grid, 256, GSMEM_BYTES>>>(u, y, grid);
}

// round 16
// speedup vs baseline: 1.2331x; 1.0281x over previous
#include <cuda_runtime.h>
#include <cuda_fp16.h>
#include <cstdint>

// ===========================================================================
// y = u @ W^T,  W = C (I-A)^{-1} B + D   (model is linear & time-invariant)
//
// Precompute via telescoping product (NO serial triangular solve):
//   (I-A)^{-1} = (I+A)(I+A^2)(I+A^4) + O(A^8),  ||A^8|| ~ 7e-7 (negligible;
//   rel_err identical to trsm path at 2.95e-4)
//   K1 (dual): A2 = A*A        | P = C*A + C
//   K2 (dual): A4 = A2*A2      | Q = P*A2 + P
//   K3:        R = Q*A4 + Q            (R = C*(I-A)^{-1})
//   K4:        W = R*B + D -> fp16 swizzled ldmatrix image
//   Small GEMMs: 2 rows/block, 256 thr, L-rows in SMEM, R streamed with an
//   EXPLICIT 16-deep load batch (bv[16]) so ptxas issues 16 LDGs in flight.
// Stage 3 gemm_kernel : persistent HMMA single-term fp16 GEMM y = uh*Wh
//   (round-12 proven version, byte-identical).
// NOTE: tcgen05 unusable (harness PTX targets compute_103, no 'a').
// (Round-15 source resubmitted verbatim: previous bench failed with a
//  device-unavailable error at harness init, before kernel evaluation.)
// ===========================================================================

#define SDIM 128
#define N_ROWS (32 * 8192)
#define TILE64 64
#define N_TILES (N_ROWS / TILE64)     // 4096

__device__ float g_A2[SDIM * SDIM];
__device__ float g_A4[SDIM * SDIM];
__device__ float g_P[SDIM * SDIM];
__device__ float g_Q[SDIM * SDIM];
__device__ float g_R[SDIM * SDIM];
__device__ __half g_Wh[SDIM * SDIM];   // swizzled ldmatrix image

__device__ __forceinline__ uint32_t smem_u32(const void* p) {
    return (uint32_t)__cvta_generic_to_shared(p);
}
__device__ __forceinline__ int swz_elem(int r, int k) {
    return r * 128 + ((((k >> 3) ^ (r & 7)) << 3) | (k & 7));
}

#define LDSM4(r, a) \
    asm volatile("ldmatrix.sync.aligned.m8n8.x4.shared.b16 {%0,%1,%2,%3}, [%4];" \
        : "=r"((r)[0]), "=r"((r)[1]), "=r"((r)[2]), "=r"((r)[3]) : "r"(a))

#define MMA16816H(d, a, b0, b1) \
    asm volatile("mma.sync.aligned.m16n8k16.row.col.f32.f16.f16.f32 " \
        "{%0,%1,%2,%3}, {%4,%5,%6,%7}, {%8,%9}, {%0,%1,%2,%3};" \
        : "+f"((d)[0]), "+f"((d)[1]), "+f"((d)[2]), "+f"((d)[3]) \
        : "r"((a)[0]), "r"((a)[1]), "r"((a)[2]), "r"((a)[3]), "r"(b0), "r"(b1))

// ===========================================================================
// Small-GEMM row kernel: O[o][:] = L[o][:]*R + (S ? S[o][:] : 0)
// 2 rows/block, 256 threads; explicit 16-deep LDG batches for MLP.
// ===========================================================================
__device__ __forceinline__ void mmrow_body(const float* __restrict__ L,
                                           const float* __restrict__ R,
                                           const float* __restrict__ S,
                                           float* __restrict__ O, int b,
                                           float sL[2][SDIM]) {
    const int tid = threadIdx.x;
    const int r = tid >> 7, d = tid & 127;
    const int o = b * 2 + r;
    sL[r][d] = L[o * SDIM + d];
    __syncthreads();
    float acc = S ? S[o * SDIM + d] : 0.f;
    const float* Rd = R + d;
    #pragma unroll
    for (int s0 = 0; s0 < SDIM; s0 += 16) {
        float bv[16];
        #pragma unroll
        for (int i = 0; i < 16; i++)
            bv[i] = Rd[(s0 + i) * SDIM];          // 16 independent LDGs
        #pragma unroll
        for (int i = 0; i < 16; i++)
            acc = fmaf(sL[r][s0 + i], bv[i], acc);
    }
    O[o * SDIM + d] = acc;
}

__global__ __launch_bounds__(256)
void mmrow_dual_kernel(const float* L0, const float* R0, const float* S0, float* O0,
                       const float* L1, const float* R1, const float* S1, float* O1) {
    __shared__ float sL[2][SDIM];
    if (blockIdx.x < 64) mmrow_body(L0, R0, S0, O0, blockIdx.x, sL);
    else                 mmrow_body(L1, R1, S1, O1, blockIdx.x - 64, sL);
}

__global__ __launch_bounds__(256)
void mmrow_kernel(const float* L, const float* R, const float* S, float* O) {
    __shared__ float sL[2][SDIM];
    mmrow_body(L, R, S, O, blockIdx.x, sL);
}

// K4: W[o][d] = sum_s R[o,s] B[s,d] + D[o,d] -> fp16 swizzled image
__global__ __launch_bounds__(256)
void wk_kernel(const float* __restrict__ B, const float* __restrict__ Dm) {
    __shared__ float sL[2][SDIM];
    const int tid = threadIdx.x;
    const int r = tid >> 7, d = tid & 127;
    const int o = blockIdx.x * 2 + r;
    sL[r][d] = g_R[o * SDIM + d];
    __syncthreads();
    float acc = Dm[o * SDIM + d];
    const float* Bd = B + d;
    #pragma unroll
    for (int s0 = 0; s0 < SDIM; s0 += 16) {
        float bv[16];
        #pragma unroll
        for (int i = 0; i < 16; i++)
            bv[i] = Bd[(s0 + i) * SDIM];
        #pragma unroll
        for (int i = 0; i < 16; i++)
            acc = fmaf(sL[r][s0 + i], bv[i], acc);
    }
    g_Wh[swz_elem(o, d)] = __float2half_rn(acc);
}

// ===========================================================================
// Stage 3: persistent HMMA GEMM, single fp16 term, 64-row tiles, 2 CTAs/SM.
// SMEM/CTA: [0,32K) Wh | U buf p at 32K + p*16K  (total 64KB)
// (byte-identical to the round-12 proven version)
// ===========================================================================
#define GSMEM_BYTES (64 * 1024)
#define UBOFF(p) (32768u + (uint32_t)(p) * 16384u)

__global__ __launch_bounds__(256, 2)
void gemm_kernel(const float* __restrict__ u, float* __restrict__ y, int grid) {
    extern __shared__ __align__(16) unsigned char sm[];
    const uint32_t sbase = smem_u32(sm);

    const int tid  = threadIdx.x;
    const int lane = tid & 31;
    const int w    = tid >> 5;
    const int rg   = w >> 2;           // 0..1 : 32-row group
    const int cq   = w & 3;            // 0..3 : 32-col quarter
    const int Rw   = rg * 32;

    // W image -> SMEM
    {
        const uint4* sh = (const uint4*)g_Wh;
        uint4* dh = (uint4*)sm;
        for (int i = tid; i < 2048; i += 256) dh[i] = sh[i];
    }

    const int a_row  = Rw + (lane & 7) + ((lane >> 3) & 1) * 8;       // + rf*16
    const int a_kadd = ((lane >> 4) & 1) * 8;
    const int b_n    = cq * 32 + (lane & 7) + ((lane >> 4) & 1) * 8;  // + ng*16
    const int b_kadd = ((lane >> 3) & 1) * 8;
    const int r7     = lane & 7;

    float4 v[8];
    int tile = blockIdx.x;

    // ---- prologue: tile0 -> buf0; prefetch tile1 into regs ---------------
    if (tile < N_TILES) {
        const float4* src = (const float4*)u + (long)tile * 2048;
        #pragma unroll
        for (int j = 0; j < 8; j++) v[j] = src[tid + 256 * j];
        #pragma unroll
        for (int j = 0; j < 8; j++) {
            int uid = tid + 256 * j;
            int row = uid >> 5, kk = uid & 31;        // kk = 8B unit in row
            float4 p0 = v[j];
            __half2 h01 = __floats2half2_rn(p0.x, p0.y);
            __half2 h23 = __floats2half2_rn(p0.z, p0.w);
            int off = row * 256 + (((kk >> 1) ^ (row & 7)) << 4) + (kk & 1) * 8;
            *(uint2*)(sm + UBOFF(0) + off) =
                make_uint2(*(uint32_t*)&h01, *(uint32_t*)&h23);
        }
    }
    if (tile + grid < N_TILES) {
        const float4* src = (const float4*)u + (long)(tile + grid) * 2048;
        #pragma unroll
        for (int j = 0; j < 8; j++) v[j] = src[tid + 256 * j];
    }
    __syncthreads();

    int p = 0;
    for (; tile < N_TILES; tile += grid) {
        const bool hasNext = (tile + grid) < N_TILES;
        const uint32_t ub  = UBOFF(p);
        const uint32_t ubn = UBOFF(p ^ 1);

        float acc[2][4][4];
        #pragma unroll
        for (int rf = 0; rf < 2; rf++)
            #pragma unroll
            for (int nt = 0; nt < 4; nt++)
                #pragma unroll
                for (int q = 0; q < 4; q++) acc[rf][nt][q] = 0.f;

        #pragma unroll
        for (int ks = 0; ks < 8; ks++) {
            const int k0 = ks * 16;
            uint32_t ah[2][4];
            {
                int mk = k0 + a_kadd;
                uint32_t ad = sbase + ub +
                    (uint32_t)(a_row * 256 + (((mk >> 3) ^ r7) << 4));
                LDSM4(ah[0], ad);
                LDSM4(ah[1], ad + 4096u);     // +16 rows
            }
            #pragma unroll
            for (int ng = 0; ng < 2; ng++) {
                int n = b_n + ng * 16;
                int mk = k0 + b_kadd;
                uint32_t bd = sbase +
                    (uint32_t)(n * 256 + (((mk >> 3) ^ r7) << 4));
                uint32_t bh[4];
                LDSM4(bh, bd);
                const int nt = ng * 2;
                MMA16816H(acc[0][nt],     ah[0], bh[0], bh[1]);
                MMA16816H(acc[0][nt + 1], ah[0], bh[2], bh[3]);
                MMA16816H(acc[1][nt],     ah[1], bh[0], bh[1]);
                MMA16816H(acc[1][nt + 1], ah[1], bh[2], bh[3]);
            }
            // interleave next-tile convert/STS chunk (1 uint2 per thread)
            if (hasNext) {
                int uid = tid + 256 * ks;
                int row = uid >> 5, kk = uid & 31;
                float4 p0 = v[ks];
                __half2 h01 = __floats2half2_rn(p0.x, p0.y);
                __half2 h23 = __floats2half2_rn(p0.z, p0.w);
                int off = row * 256 + (((kk >> 1) ^ (row & 7)) << 4) + (kk & 1) * 8;
                *(uint2*)(sm + ubn + off) =
                    make_uint2(*(uint32_t*)&h01, *(uint32_t*)&h23);
            }
        }

        // epilogue: fragments -> y
        {
            const int q = lane >> 2, s2 = (lane & 3) * 2;
            #pragma unroll
            for (int rf = 0; rf < 2; rf++) {
                long grow = (long)tile * TILE64 + Rw + rf * 16 + q;
                float* yp0 = y + grow * SDIM + cq * 32 + s2;
                #pragma unroll
                for (int nt = 0; nt < 4; nt++) {
                    *(float2*)(yp0 + nt * 8) =
                        make_float2(acc[rf][nt][0], acc[rf][nt][1]);
                    *(float2*)(yp0 + 8 * SDIM + nt * 8) =
                        make_float2(acc[rf][nt][2], acc[rf][nt][3]);
                }
            }
        }

        // prefetch tile t+2 into regs
        if (tile + 2 * grid < N_TILES) {
            const float4* src = (const float4*)u + (long)(tile + 2 * grid) * 2048;
            #pragma unroll
            for (int j = 0; j < 8; j++) v[j] = src[tid + 256 * j];
        }
        __syncthreads();
        p ^= 1;
    }
}

// ===========================================================================
extern "C" void kernel_launch(void* const* d_in, const int* in_sizes, int n_in,
                              void* d_out, int out_size) {
    const float* u = (const float*)d_in[0];
    const float* A = (const float*)d_in[1];
    const float* B = (const float*)d_in[2];
    const float* C = (const float*)d_in[3];
    const float* D = (const float*)d_in[4];
    float* y = (float*)d_out;

    int sms = 0, dev = 0;
    cudaGetDevice(&dev);
    cudaDeviceGetAttribute(&sms, cudaDevAttrMultiProcessorCount, dev);
    if (sms <= 0) sms = 148;

    cudaFuncSetAttribute(gemm_kernel, cudaFuncAttributeMaxDynamicSharedMemorySize, GSMEM_BYTES);

    float *dA2, *dA4, *dP, *dQ, *dR;
    cudaGetSymbolAddress((void**)&dA2, g_A2);
    cudaGetSymbolAddress((void**)&dA4, g_A4);
    cudaGetSymbolAddress((void**)&dP,  g_P);
    cudaGetSymbolAddress((void**)&dQ,  g_Q);
    cudaGetSymbolAddress((void**)&dR,  g_R);

    // K1: A2 = A*A            | P = C*A + C
    mmrow_dual_kernel<<<128, 256>>>(A, A, nullptr, dA2,
                                    C, A, C, dP);
    // K2: A4 = A2*A2          | Q = P*A2 + P
    mmrow_dual_kernel<<<128, 256>>>(dA2, dA2, nullptr, dA4,
                                    dP, dA2, dP, dQ);
    // K3: R = Q*A4 + Q
    mmrow_kernel<<<64, 256>>>(dQ, dA4, dQ, dR);
    // K4: W = R*B + D -> fp16 image
    wk_kernel<<<64, 256>>>(B, D);

    const int grid = 2 * sms;
    gemm_kernel<<<grid, 256, GSMEM_BYTES>>>(u, y, grid);
}

// round 17
// speedup vs baseline: 1.3070x; 1.0600x over previous
#include <cuda_runtime.h>
#include <cuda_fp16.h>
#include <cstdint>

// ===========================================================================
// y = u @ W^T,  W = C (I-A)^{-1} B + D   (model is linear & time-invariant)
//
// Precompute via telescoping product (NO serial triangular solve):
//   (I-A)^{-1} = (I+A)(I+A^2)(I+A^4) + O(A^8),  ||A^8|| ~ 7e-7 (negligible)
//   K1 (dual): A2 = A*A        | P = C*A + C        (R = A   staged in SMEM)
//   K2 (dual): A4 = A2*A2      | Q = P*A2 + P       (R = A2  staged in SMEM)
//   K3:        R  = Q*A4 + Q                        (R = A4  staged in SMEM)
//   K4:        W  = R*B + D -> fp16 swizzled image  (R = B   staged in SMEM)
//   Small GEMMs: 2 output rows/block, 256 thr; the full 64KB right operand
//   is staged in dynamic SMEM (16 coalesced f4 LDGs/thread, MLP 16, ONE
//   latency exposure) -> compute runs entirely from SMEM.
// Stage 3 gemm_kernel : persistent HMMA single-term fp16 GEMM y = uh*Wh
//   (round-12 proven version, byte-identical).
// NOTE: tcgen05 unusable (harness PTX targets compute_103, no 'a').
// ===========================================================================

#define SDIM 128
#define N_ROWS (32 * 8192)
#define TILE64 64
#define N_TILES (N_ROWS / TILE64)     // 4096

__device__ float g_A2[SDIM * SDIM];
__device__ float g_A4[SDIM * SDIM];
__device__ float g_P[SDIM * SDIM];
__device__ float g_Q[SDIM * SDIM];
__device__ float g_R[SDIM * SDIM];
__device__ __half g_Wh[SDIM * SDIM];   // swizzled ldmatrix image

__device__ __forceinline__ uint32_t smem_u32(const void* p) {
    return (uint32_t)__cvta_generic_to_shared(p);
}
__device__ __forceinline__ int swz_elem(int r, int k) {
    return r * 128 + ((((k >> 3) ^ (r & 7)) << 3) | (k & 7));
}

#define LDSM4(r, a) \
    asm volatile("ldmatrix.sync.aligned.m8n8.x4.shared.b16 {%0,%1,%2,%3}, [%4];" \
        : "=r"((r)[0]), "=r"((r)[1]), "=r"((r)[2]), "=r"((r)[3]) : "r"(a))

#define MMA16816H(d, a, b0, b1) \
    asm volatile("mma.sync.aligned.m16n8k16.row.col.f32.f16.f16.f32 " \
        "{%0,%1,%2,%3}, {%4,%5,%6,%7}, {%8,%9}, {%0,%1,%2,%3};" \
        : "+f"((d)[0]), "+f"((d)[1]), "+f"((d)[2]), "+f"((d)[3]) \
        : "r"((a)[0]), "r"((a)[1]), "r"((a)[2]), "r"((a)[3]), "r"(b0), "r"(b1))

// ===========================================================================
// Small-GEMM: O[o][:] = L[o][:]*R + (S ? S[o][:] : 0), 2 rows per block.
// Full R (64KB) staged in dynamic SMEM; L rows in static SMEM.
// ===========================================================================
__device__ __forceinline__ void smg_body(const float* __restrict__ L,
                                         const float* __restrict__ R,
                                         const float* __restrict__ S,
                                         float* __restrict__ O, int b,
                                         float* sR, float sL[2][SDIM]) {
    const int tid = threadIdx.x;
    const int r = tid >> 7, d = tid & 127;
    const int o = b * 2 + r;

    // stage R: 4096 float4, 16 per thread, all independent (MLP 16)
    const float4* R4 = (const float4*)R;
    float4* sR4 = (float4*)sR;
    #pragma unroll
    for (int i = 0; i < 16; i++) sR4[tid + 256 * i] = R4[tid + 256 * i];
    // stage L rows (coalesced, 1 per thread)
    sL[r][d] = L[o * SDIM + d];
    __syncthreads();

    float a0 = 0.f, a1 = 0.f, a2 = 0.f, a3 = 0.f;
    #pragma unroll 8
    for (int s = 0; s < SDIM; s += 4) {
        a0 = fmaf(sL[r][s + 0], sR[(s + 0) * SDIM + d], a0);
        a1 = fmaf(sL[r][s + 1], sR[(s + 1) * SDIM + d], a1);
        a2 = fmaf(sL[r][s + 2], sR[(s + 2) * SDIM + d], a2);
        a3 = fmaf(sL[r][s + 3], sR[(s + 3) * SDIM + d], a3);
    }
    float acc = ((a0 + a1) + (a2 + a3)) + (S ? S[o * SDIM + d] : 0.f);
    O[o * SDIM + d] = acc;
}

__global__ __launch_bounds__(256)
void smg_dual_kernel(const float* L0, const float* R0, const float* S0, float* O0,
                     const float* L1, const float* R1, const float* S1, float* O1) {
    extern __shared__ float sR[];
    __shared__ float sL[2][SDIM];
    if (blockIdx.x < 64) smg_body(L0, R0, S0, O0, blockIdx.x, sR, sL);
    else                 smg_body(L1, R1, S1, O1, blockIdx.x - 64, sR, sL);
}

__global__ __launch_bounds__(256)
void smg_kernel(const float* L, const float* R, const float* S, float* O) {
    extern __shared__ float sR[];
    __shared__ float sL[2][SDIM];
    smg_body(L, R, S, O, blockIdx.x, sR, sL);
}

// K4: W[o][d] = sum_s R[o,s] B[s,d] + D[o,d] -> fp16 swizzled image
__global__ __launch_bounds__(256)
void wk_kernel(const float* __restrict__ B, const float* __restrict__ Dm) {
    extern __shared__ float sR[];
    __shared__ float sL[2][SDIM];
    const int tid = threadIdx.x;
    const int r = tid >> 7, d = tid & 127;
    const int o = blockIdx.x * 2 + r;

    const float4* B4 = (const float4*)B;
    float4* sR4 = (float4*)sR;
    #pragma unroll
    for (int i = 0; i < 16; i++) sR4[tid + 256 * i] = B4[tid + 256 * i];
    sL[r][d] = g_R[o * SDIM + d];
    __syncthreads();

    float a0 = 0.f, a1 = 0.f, a2 = 0.f, a3 = 0.f;
    #pragma unroll 8
    for (int s = 0; s < SDIM; s += 4) {
        a0 = fmaf(sL[r][s + 0], sR[(s + 0) * SDIM + d], a0);
        a1 = fmaf(sL[r][s + 1], sR[(s + 1) * SDIM + d], a1);
        a2 = fmaf(sL[r][s + 2], sR[(s + 2) * SDIM + d], a2);
        a3 = fmaf(sL[r][s + 3], sR[(s + 3) * SDIM + d], a3);
    }
    float acc = ((a0 + a1) + (a2 + a3)) + Dm[o * SDIM + d];
    g_Wh[swz_elem(o, d)] = __float2half_rn(acc);
}

// ===========================================================================
// Stage 3: persistent HMMA GEMM, single fp16 term, 64-row tiles, 2 CTAs/SM.
// SMEM/CTA: [0,32K) Wh | U buf p at 32K + p*16K  (total 64KB)
// (byte-identical to the round-12 proven version)
// ===========================================================================
#define GSMEM_BYTES (64 * 1024)
#define UBOFF(p) (32768u + (uint32_t)(p) * 16384u)

__global__ __launch_bounds__(256, 2)
void gemm_kernel(const float* __restrict__ u, float* __restrict__ y, int grid) {
    extern __shared__ __align__(16) unsigned char sm[];
    const uint32_t sbase = smem_u32(sm);

    const int tid  = threadIdx.x;
    const int lane = tid & 31;
    const int w    = tid >> 5;
    const int rg   = w >> 2;           // 0..1 : 32-row group
    const int cq   = w & 3;            // 0..3 : 32-col quarter
    const int Rw   = rg * 32;

    // W image -> SMEM
    {
        const uint4* sh = (const uint4*)g_Wh;
        uint4* dh = (uint4*)sm;
        for (int i = tid; i < 2048; i += 256) dh[i] = sh[i];
    }

    const int a_row  = Rw + (lane & 7) + ((lane >> 3) & 1) * 8;       // + rf*16
    const int a_kadd = ((lane >> 4) & 1) * 8;
    const int b_n    = cq * 32 + (lane & 7) + ((lane >> 4) & 1) * 8;  // + ng*16
    const int b_kadd = ((lane >> 3) & 1) * 8;
    const int r7     = lane & 7;

    float4 v[8];
    int tile = blockIdx.x;

    // ---- prologue: tile0 -> buf0; prefetch tile1 into regs ---------------
    if (tile < N_TILES) {
        const float4* src = (const float4*)u + (long)tile * 2048;
        #pragma unroll
        for (int j = 0; j < 8; j++) v[j] = src[tid + 256 * j];
        #pragma unroll
        for (int j = 0; j < 8; j++) {
            int uid = tid + 256 * j;
            int row = uid >> 5, kk = uid & 31;        // kk = 8B unit in row
            float4 p0 = v[j];
            __half2 h01 = __floats2half2_rn(p0.x, p0.y);
            __half2 h23 = __floats2half2_rn(p0.z, p0.w);
            int off = row * 256 + (((kk >> 1) ^ (row & 7)) << 4) + (kk & 1) * 8;
            *(uint2*)(sm + UBOFF(0) + off) =
                make_uint2(*(uint32_t*)&h01, *(uint32_t*)&h23);
        }
    }
    if (tile + grid < N_TILES) {
        const float4* src = (const float4*)u + (long)(tile + grid) * 2048;
        #pragma unroll
        for (int j = 0; j < 8; j++) v[j] = src[tid + 256 * j];
    }
    __syncthreads();

    int p = 0;
    for (; tile < N_TILES; tile += grid) {
        const bool hasNext = (tile + grid) < N_TILES;
        const uint32_t ub  = UBOFF(p);
        const uint32_t ubn = UBOFF(p ^ 1);

        float acc[2][4][4];
        #pragma unroll
        for (int rf = 0; rf < 2; rf++)
            #pragma unroll
            for (int nt = 0; nt < 4; nt++)
                #pragma unroll
                for (int q = 0; q < 4; q++) acc[rf][nt][q] = 0.f;

        #pragma unroll
        for (int ks = 0; ks < 8; ks++) {
            const int k0 = ks * 16;
            uint32_t ah[2][4];
            {
                int mk = k0 + a_kadd;
                uint32_t ad = sbase + ub +
                    (uint32_t)(a_row * 256 + (((mk >> 3) ^ r7) << 4));
                LDSM4(ah[0], ad);
                LDSM4(ah[1], ad + 4096u);     // +16 rows
            }
            #pragma unroll
            for (int ng = 0; ng < 2; ng++) {
                int n = b_n + ng * 16;
                int mk = k0 + b_kadd;
                uint32_t bd = sbase +
                    (uint32_t)(n * 256 + (((mk >> 3) ^ r7) << 4));
                uint32_t bh[4];
                LDSM4(bh, bd);
                const int nt = ng * 2;
                MMA16816H(acc[0][nt],     ah[0], bh[0], bh[1]);
                MMA16816H(acc[0][nt + 1], ah[0], bh[2], bh[3]);
                MMA16816H(acc[1][nt],     ah[1], bh[0], bh[1]);
                MMA16816H(acc[1][nt + 1], ah[1], bh[2], bh[3]);
            }
            // interleave next-tile convert/STS chunk (1 uint2 per thread)
            if (hasNext) {
                int uid = tid + 256 * ks;
                int row = uid >> 5, kk = uid & 31;
                float4 p0 = v[ks];
                __half2 h01 = __floats2half2_rn(p0.x, p0.y);
                __half2 h23 = __floats2half2_rn(p0.z, p0.w);
                int off = row * 256 + (((kk >> 1) ^ (row & 7)) << 4) + (kk & 1) * 8;
                *(uint2*)(sm + ubn + off) =
                    make_uint2(*(uint32_t*)&h01, *(uint32_t*)&h23);
            }
        }

        // epilogue: fragments -> y
        {
            const int q = lane >> 2, s2 = (lane & 3) * 2;
            #pragma unroll
            for (int rf = 0; rf < 2; rf++) {
                long grow = (long)tile * TILE64 + Rw + rf * 16 + q;
                float* yp0 = y + grow * SDIM + cq * 32 + s2;
                #pragma unroll
                for (int nt = 0; nt < 4; nt++) {
                    *(float2*)(yp0 + nt * 8) =
                        make_float2(acc[rf][nt][0], acc[rf][nt][1]);
                    *(float2*)(yp0 + 8 * SDIM + nt * 8) =
                        make_float2(acc[rf][nt][2], acc[rf][nt][3]);
                }
            }
        }

        // prefetch tile t+2 into regs
        if (tile + 2 * grid < N_TILES) {
            const float4* src = (const float4*)u + (long)(tile + 2 * grid) * 2048;
            #pragma unroll
            for (int j = 0; j < 8; j++) v[j] = src[tid + 256 * j];
        }
        __syncthreads();
        p ^= 1;
    }
}

// ===========================================================================
extern "C" void kernel_launch(void* const* d_in, const int* in_sizes, int n_in,
                              void* d_out, int out_size) {
    const float* u = (const float*)d_in[0];
    const float* A = (const float*)d_in[1];
    const float* B = (const float*)d_in[2];
    const float* C = (const float*)d_in[3];
    const float* D = (const float*)d_in[4];
    float* y = (float*)d_out;

    int sms = 0, dev = 0;
    cudaGetDevice(&dev);
    cudaDeviceGetAttribute(&sms, cudaDevAttrMultiProcessorCount, dev);
    if (sms <= 0) sms = 148;

    const int smg_smem = SDIM * SDIM * (int)sizeof(float);   // 64KB
    cudaFuncSetAttribute(smg_dual_kernel, cudaFuncAttributeMaxDynamicSharedMemorySize, smg_smem);
    cudaFuncSetAttribute(smg_kernel,      cudaFuncAttributeMaxDynamicSharedMemorySize, smg_smem);
    cudaFuncSetAttribute(wk_kernel,       cudaFuncAttributeMaxDynamicSharedMemorySize, smg_smem);
    cudaFuncSetAttribute(gemm_kernel,     cudaFuncAttributeMaxDynamicSharedMemorySize, GSMEM_BYTES);

    float *dA2, *dA4, *dP, *dQ, *dR;
    cudaGetSymbolAddress((void**)&dA2, g_A2);
    cudaGetSymbolAddress((void**)&dA4, g_A4);
    cudaGetSymbolAddress((void**)&dP,  g_P);
    cudaGetSymbolAddress((void**)&dQ,  g_Q);
    cudaGetSymbolAddress((void**)&dR,  g_R);

    // K1: A2 = A*A            | P = C*A + C
    smg_dual_kernel<<<128, 256, smg_smem>>>(A, A, nullptr, dA2,
                                            C, A, C, dP);
    // K2: A4 = A2*A2          | Q = P*A2 + P
    smg_dual_kernel<<<128, 256, smg_smem>>>(dA2, dA2, nullptr, dA4,
                                            dP, dA2, dP, dQ);
    // K3: R = Q*A4 + Q
    smg_kernel<<<64, 256, smg_smem>>>(dQ, dA4, dQ, dR);
    // K4: W = R*B + D -> fp16 image
    wk_kernel<<<64, 256, smg_smem>>>(B, D);

    const int grid = 2 * sms;
    gemm_kernel<<<grid, 256, GSMEM_BYTES>>>(u, y, grid);
}